// round 1
// baseline (speedup 1.0000x reference)
#include <cuda_runtime.h>
#include <math.h>

#define N_NODES 12800
#define N_EDGES 204800
#define DIM 16
#define EDGE_DIM 4
#define NFEAT 3

// ---------------- scratch (static device memory, no allocs) ----------------
__device__ float g_out[N_NODES * DIM];          // node state (h == out)
__device__ float g_P[N_NODES * DIM * DIM];      // per-node contracted weights, 13 MB
__device__ float g_xb[N_NODES * DIM];           // per-node bias term
__device__ float g_he[N_EDGES * DIM];           // edge hidden (fixed), 13 MB
__device__ float g_aggr[N_NODES * DIM];         // scatter accumulator
__device__ float g_deg[N_NODES];                // in-degree -> inverse degree

// ---------------- setup kernels ----------------
__global__ void k_zero_deg() {
    int i = blockIdx.x * blockDim.x + threadIdx.x;
    if (i < N_NODES) g_deg[i] = 0.0f;
}

__global__ void k_lin0(const float* __restrict__ x, const float* __restrict__ w,
                       const float* __restrict__ b) {
    int i = blockIdx.x * blockDim.x + threadIdx.x;  // n*16 + k
    if (i >= N_NODES * DIM) return;
    int n = i >> 4, k = i & 15;
    float acc = b[k];
#pragma unroll
    for (int c = 0; c < NFEAT; ++c) acc += x[n * NFEAT + c] * w[k * NFEAT + c];
    g_out[i] = fmaxf(acc, 0.0f);
}

// edge hidden h_e = relu(edge_attr @ nn1_w^T + nn1_b); also accumulate in-degree
__global__ void k_edge_pre(const float* __restrict__ ea, const int* __restrict__ ei,
                           const float* __restrict__ w, const float* __restrict__ b) {
    int i = blockIdx.x * blockDim.x + threadIdx.x;  // e*16 + j
    if (i >= N_EDGES * DIM) return;
    int e = i >> 4, j = i & 15;
    float acc = b[j];
#pragma unroll
    for (int c = 0; c < EDGE_DIM; ++c) acc += ea[e * EDGE_DIM + c] * w[j * EDGE_DIM + c];
    g_he[i] = fmaxf(acc, 0.0f);
    if (j == 0) atomicAdd(&g_deg[ei[N_EDGES + e]], 1.0f);
}

__global__ void k_invdeg() {
    int i = blockIdx.x * blockDim.x + threadIdx.x;
    if (i < N_NODES) g_deg[i] = 1.0f / fmaxf(g_deg[i], 1.0f);
}

// ---------------- per-round kernels ----------------
// P[n,k,j] = sum_d out[n,d] * W2[(d*16+k)*16+j] ; xb[n,k] = sum_d out[n,d]*b2[d*16+k]
// Also zeroes g_aggr for this round (safe: runs after previous round's update).
__global__ void k_nodeP(const float* __restrict__ w2, const float* __restrict__ b2) {
    __shared__ float s_w2[DIM * DIM * DIM];   // 16 KB
    __shared__ float s_b2[DIM * DIM];
    __shared__ float s_out[16][DIM];
    int tid = threadIdx.x;                    // 256 threads = 16 nodes x 16 k
    for (int i = tid; i < DIM * DIM * DIM; i += 256) s_w2[i] = w2[i];
    for (int i = tid; i < DIM * DIM; i += 256) s_b2[i] = b2[i];
    int ln = tid >> 4, k = tid & 15;
    int n = blockIdx.x * 16 + ln;
    s_out[ln][k] = g_out[n * DIM + k];
    g_aggr[n * DIM + k] = 0.0f;
    __syncthreads();

    float a[DIM];
#pragma unroll
    for (int j = 0; j < DIM; ++j) a[j] = 0.0f;
    float xb = 0.0f;
#pragma unroll
    for (int d = 0; d < DIM; ++d) {
        float od = s_out[ln][d];
        const float* row = &s_w2[(d * DIM + k) * DIM];
#pragma unroll
        for (int j = 0; j < DIM; ++j) a[j] += od * row[j];
        xb += od * s_b2[d * DIM + k];
    }
    float* dst = &g_P[(n * DIM + k) * DIM];
#pragma unroll
    for (int j = 0; j < DIM; ++j) dst[j] = a[j];
    g_xb[n * DIM + k] = xb;
}

// msg[e,k] = dot(h_e, P[src,k,:]) + xb[src,k]; atomic add into aggr[dst,k]
__global__ void k_edge(const int* __restrict__ ei) {
    int tid = blockIdx.x * blockDim.x + threadIdx.x;  // e*16 + k
    int e = tid >> 4;
    if (e >= N_EDGES) return;
    int k = tid & 15;
    int src = __ldg(&ei[e]);
    int dst = __ldg(&ei[N_EDGES + e]);

    const float4* hp = (const float4*)&g_he[e * DIM];
    float4 h0 = hp[0], h1 = hp[1], h2 = hp[2], h3 = hp[3];
    const float4* pp = (const float4*)&g_P[(src * DIM + k) * DIM];
    float4 p0 = pp[0], p1 = pp[1], p2 = pp[2], p3 = pp[3];

    float m = __ldg(&g_xb[src * DIM + k]);
    m += h0.x * p0.x + h0.y * p0.y + h0.z * p0.z + h0.w * p0.w;
    m += h1.x * p1.x + h1.y * p1.y + h1.z * p1.z + h1.w * p1.w;
    m += h2.x * p2.x + h2.y * p2.y + h2.z * p2.z + h2.w * p2.w;
    m += h3.x * p3.x + h3.y * p3.y + h3.z * p3.z + h3.w * p3.w;

    atomicAdd(&g_aggr[dst * DIM + k], m);
}

// m = relu(aggr*invdeg + out@conv_root + conv_bias); GRU step; write new h
__global__ void k_update(const float* __restrict__ cr, const float* __restrict__ cb,
                         const float* __restrict__ wih, const float* __restrict__ whh,
                         const float* __restrict__ bih, const float* __restrict__ bhh,
                         float* __restrict__ outw) {
    __shared__ float s_cr[DIM * DIM];
    __shared__ float s_wih[3 * DIM * DIM];
    __shared__ float s_whh[3 * DIM * DIM];
    __shared__ float s_out[16][DIM + 1];
    __shared__ float s_m[16][DIM + 1];
    int tid = threadIdx.x;                    // 256 = 16 nodes x 16 k
    for (int i = tid; i < DIM * DIM; i += 256) s_cr[i] = cr[i];
    for (int i = tid; i < 3 * DIM * DIM; i += 256) { s_wih[i] = wih[i]; s_whh[i] = whh[i]; }
    int ln = tid >> 4, k = tid & 15;
    int n = blockIdx.x * 16 + ln;
    float hprev = g_out[n * DIM + k];
    s_out[ln][k] = hprev;
    __syncthreads();

    float invd = g_deg[n];                    // already inverted
    float acc = g_aggr[n * DIM + k] * invd + cb[k];
#pragma unroll
    for (int d = 0; d < DIM; ++d) acc += s_out[ln][d] * s_cr[d * DIM + k];
    float m = fmaxf(acc, 0.0f);
    s_m[ln][k] = m;
    __syncthreads();

    float gr = bih[k], gz = bih[k + 16], gn = bih[k + 32];
    float hr = bhh[k], hz = bhh[k + 16], hn = bhh[k + 32];
#pragma unroll
    for (int d = 0; d < DIM; ++d) {
        float md = s_m[ln][d], hd = s_out[ln][d];
        gr += md * s_wih[k * DIM + d];
        gz += md * s_wih[(k + 16) * DIM + d];
        gn += md * s_wih[(k + 32) * DIM + d];
        hr += hd * s_whh[k * DIM + d];
        hz += hd * s_whh[(k + 16) * DIM + d];
        hn += hd * s_whh[(k + 32) * DIM + d];
    }
    float r = 1.0f / (1.0f + expf(-(gr + hr)));
    float z = 1.0f / (1.0f + expf(-(gz + hz)));
    float nh = tanhf(gn + r * hn);
    outw[n * DIM + k] = (1.0f - z) * nh + z * hprev;
}

// ---------------- host launcher ----------------
extern "C" void kernel_launch(void* const* d_in, const int* in_sizes, int n_in,
                              void* d_out, int out_size) {
    const float* x         = (const float*)d_in[0];
    const int*   ei        = (const int*)  d_in[1];
    const float* ea        = (const float*)d_in[2];
    const float* lin0_w    = (const float*)d_in[3];
    const float* lin0_b    = (const float*)d_in[4];
    const float* nn1_w     = (const float*)d_in[5];
    const float* nn1_b     = (const float*)d_in[6];
    const float* nn2_w     = (const float*)d_in[7];
    const float* nn2_b     = (const float*)d_in[8];
    const float* conv_root = (const float*)d_in[9];
    const float* conv_bias = (const float*)d_in[10];
    const float* w_ih      = (const float*)d_in[11];
    const float* w_hh      = (const float*)d_in[12];
    const float* b_ih      = (const float*)d_in[13];
    const float* b_hh      = (const float*)d_in[14];

    float* outp = nullptr;
    cudaGetSymbolAddress((void**)&outp, g_out);

    k_zero_deg<<<(N_NODES + 255) / 256, 256>>>();
    k_lin0<<<(N_NODES * DIM + 255) / 256, 256>>>(x, lin0_w, lin0_b);
    k_edge_pre<<<(N_EDGES * DIM + 255) / 256, 256>>>(ea, ei, nn1_w, nn1_b);
    k_invdeg<<<(N_NODES + 255) / 256, 256>>>();

    for (int r = 0; r < 6; ++r) {
        k_nodeP<<<N_NODES / 16, 256>>>(nn2_w, nn2_b);
        k_edge<<<(N_EDGES * DIM) / 256, 256>>>(ei);
        k_update<<<N_NODES / 16, 256>>>(conv_root, conv_bias, w_ih, w_hh, b_ih, b_hh,
                                        r == 5 ? (float*)d_out : outp);
    }
}

// round 2
// speedup vs baseline: 1.9015x; 1.9015x over previous
#include <cuda_runtime.h>
#include <math.h>

#define N_NODES 12800
#define N_EDGES 204800
#define DIM 16
#define EDGE_DIM 4
#define NFEAT 3

// ---------------- scratch (static device memory, no allocs) ----------------
__device__ float g_out[N_NODES * DIM];          // node state
__device__ float g_he[N_EDGES * DIM];           // edge hidden (fixed per call)
__device__ float g_msg[N_EDGES * DIM];          // messages, stored in DST-SORTED order
__device__ int   g_src_cnt[N_NODES];
__device__ int   g_dst_cnt[N_NODES];
__device__ int   g_src_off[N_NODES + 1];
__device__ int   g_dst_off[N_NODES + 1];
__device__ int   g_src_cur[N_NODES];
__device__ int   g_dst_cur[N_NODES];
__device__ int   g_src_list[N_EDGES];           // edge ids sorted by src
__device__ int   g_e2q[N_EDGES];                // edge id -> dst-sorted slot
__device__ float g_invdeg[N_NODES];

// ---------------- setup ----------------
__global__ void k_init() {
    int i = blockIdx.x * blockDim.x + threadIdx.x;
    if (i < N_NODES) { g_src_cnt[i] = 0; g_dst_cnt[i] = 0; }
}

__global__ void k_lin0(const float* __restrict__ x, const float* __restrict__ w,
                       const float* __restrict__ b) {
    int i = blockIdx.x * blockDim.x + threadIdx.x;
    if (i >= N_NODES * DIM) return;
    int n = i >> 4, k = i & 15;
    float acc = b[k];
#pragma unroll
    for (int c = 0; c < NFEAT; ++c) acc += x[n * NFEAT + c] * w[k * NFEAT + c];
    g_out[i] = fmaxf(acc, 0.0f);
}

// h_e = relu(edge_attr @ nn1_w^T + nn1_b); also histogram src/dst counts
__global__ void k_hepre(const float* __restrict__ ea, const int* __restrict__ ei,
                        const float* __restrict__ w, const float* __restrict__ b) {
    int i = blockIdx.x * blockDim.x + threadIdx.x;
    if (i >= N_EDGES * DIM) return;
    int e = i >> 4, j = i & 15;
    float acc = b[j];
#pragma unroll
    for (int c = 0; c < EDGE_DIM; ++c) acc += ea[e * EDGE_DIM + c] * w[j * EDGE_DIM + c];
    g_he[i] = fmaxf(acc, 0.0f);
    if (j == 0) {
        atomicAdd(&g_src_cnt[ei[e]], 1);
        atomicAdd(&g_dst_cnt[ei[N_EDGES + e]], 1);
    }
}

// exclusive scan of both count arrays (block 0: src, block 1: dst); init cursors;
// dst block also writes inverse degree.
__global__ void k_scan() {
    const int T = 1024;
    const int per = (N_NODES + T - 1) / T;   // 13
    int which = blockIdx.x;
    int* cnt = which ? g_dst_cnt : g_src_cnt;
    int* off = which ? g_dst_off : g_src_off;
    int* cur = which ? g_dst_cur : g_src_cur;
    __shared__ int s[T];
    int tid = threadIdx.x;
    int base = tid * per;
    int local = 0;
    for (int i = 0; i < per; ++i) {
        int idx = base + i;
        if (idx < N_NODES) local += cnt[idx];
    }
    s[tid] = local;
    __syncthreads();
    for (int st = 1; st < T; st <<= 1) {
        int v = 0;
        if (tid >= st) v = s[tid - st];
        __syncthreads();
        if (tid >= st) s[tid] += v;
        __syncthreads();
    }
    int run = tid ? s[tid - 1] : 0;
    for (int i = 0; i < per; ++i) {
        int idx = base + i;
        if (idx < N_NODES) {
            off[idx] = run;
            cur[idx] = run;
            if (which) g_invdeg[idx] = 1.0f / fmaxf((float)cnt[idx], 1.0f);
            run += cnt[idx];
        }
    }
    if (tid == T - 1) off[N_NODES] = s[T - 1];
}

__global__ void k_scatter(const int* __restrict__ ei) {
    int e = blockIdx.x * blockDim.x + threadIdx.x;
    if (e >= N_EDGES) return;
    int s = ei[e];
    int p = atomicAdd(&g_src_cur[s], 1);
    g_src_list[p] = e;
    int d = ei[N_EDGES + e];
    int q = atomicAdd(&g_dst_cur[d], 1);
    g_e2q[e] = q;
}

// ---------------- per-round kernels ----------------
// Phase A: per src node, compute P row in registers, stream outgoing edges,
// write msg into dst-sorted slots. P[k][j] = sum_d out[n,d]*W2[d*256+k*16+j].
__global__ void k_msg(const float* __restrict__ w2, const float* __restrict__ b2) {
    __shared__ float s_w2t[DIM * DIM * DIM];   // transposed: [d][j][k] (16 KB)
    __shared__ float s_b2[DIM * DIM];          // [d][k]
    __shared__ float s_out[16][DIM];
    int tid = threadIdx.x;                     // 256 = 16 nodes x 16 k
    for (int i = tid; i < DIM * DIM * DIM; i += 256) {
        int d = i >> 8, k = (i >> 4) & 15, j = i & 15;
        s_w2t[d * 256 + j * 16 + k] = w2[i];
    }
    for (int i = tid; i < DIM * DIM; i += 256) s_b2[i] = b2[i];
    int ln = tid >> 4, k = tid & 15;
    int n = blockIdx.x * 16 + ln;
    s_out[ln][k] = g_out[n * DIM + k];
    __syncthreads();

    float p[DIM];
#pragma unroll
    for (int j = 0; j < DIM; ++j) p[j] = 0.0f;
    float xb = 0.0f;
#pragma unroll
    for (int d = 0; d < DIM; ++d) {
        float od = s_out[ln][d];
        const float* row = &s_w2t[d * 256 + k];   // + j*16, conflict-free across k
#pragma unroll
        for (int j = 0; j < DIM; ++j) p[j] += od * row[j * 16];
        xb += od * s_b2[d * DIM + k];
    }

    int beg = g_src_off[n], end = g_src_off[n + 1];
    for (int i = beg; i < end; ++i) {
        int e = g_src_list[i];                 // broadcast across the 16-lane group
        int q = g_e2q[e];
        const float4* hp = (const float4*)&g_he[e * DIM];
        float4 h0 = hp[0], h1 = hp[1], h2 = hp[2], h3 = hp[3];
        float m = xb;
        m += h0.x * p[0] + h0.y * p[1] + h0.z * p[2] + h0.w * p[3];
        m += h1.x * p[4] + h1.y * p[5] + h1.z * p[6] + h1.w * p[7];
        m += h2.x * p[8] + h2.y * p[9] + h2.z * p[10] + h2.w * p[11];
        m += h3.x * p[12] + h3.y * p[13] + h3.z * p[14] + h3.w * p[15];
        g_msg[q * DIM + k] = m;                // coalesced 64B per edge
    }
}

// Phase B: contiguous gather of incoming messages, mean, root matmul, ReLU, GRU.
__global__ void k_upd(const float* __restrict__ cr, const float* __restrict__ cb,
                      const float* __restrict__ wih, const float* __restrict__ whh,
                      const float* __restrict__ bih, const float* __restrict__ bhh,
                      float* __restrict__ outw) {
    __shared__ float s_cr[DIM * DIM];          // [d][k] (stride-1 in k: conflict-free)
    __shared__ float s_wih[DIM * 3 * DIM];     // transposed: [d][r]
    __shared__ float s_whh[DIM * 3 * DIM];
    __shared__ float s_out[16][DIM];
    __shared__ float s_m[16][DIM];
    int tid = threadIdx.x;
    for (int i = tid; i < DIM * DIM; i += 256) s_cr[i] = cr[i];
    for (int i = tid; i < 3 * DIM * DIM; i += 256) {
        int r = i >> 4, d = i & 15;
        s_wih[d * 48 + r] = wih[i];
        s_whh[d * 48 + r] = whh[i];
    }
    int ln = tid >> 4, k = tid & 15;
    int n = blockIdx.x * 16 + ln;
    float hprev = g_out[n * DIM + k];
    s_out[ln][k] = hprev;
    __syncthreads();

    int beg = g_dst_off[n], end = g_dst_off[n + 1];
    float acc = 0.0f;
    for (int q = beg; q < end; ++q) acc += g_msg[q * DIM + k];  // contiguous
    acc = acc * g_invdeg[n] + cb[k];
#pragma unroll
    for (int d = 0; d < DIM; ++d) acc += s_out[ln][d] * s_cr[d * DIM + k];
    float m = fmaxf(acc, 0.0f);
    s_m[ln][k] = m;
    __syncthreads();

    float gr = bih[k], gz = bih[k + 16], gn = bih[k + 32];
    float hr = bhh[k], hz = bhh[k + 16], hn = bhh[k + 32];
#pragma unroll
    for (int d = 0; d < DIM; ++d) {
        float md = s_m[ln][d], hd = s_out[ln][d];
        gr += md * s_wih[d * 48 + k];
        gz += md * s_wih[d * 48 + k + 16];
        gn += md * s_wih[d * 48 + k + 32];
        hr += hd * s_whh[d * 48 + k];
        hz += hd * s_whh[d * 48 + k + 16];
        hn += hd * s_whh[d * 48 + k + 32];
    }
    float r = 1.0f / (1.0f + expf(-(gr + hr)));
    float z = 1.0f / (1.0f + expf(-(gz + hz)));
    float nh = tanhf(gn + r * hn);
    outw[n * DIM + k] = (1.0f - z) * nh + z * hprev;
}

// ---------------- host launcher ----------------
extern "C" void kernel_launch(void* const* d_in, const int* in_sizes, int n_in,
                              void* d_out, int out_size) {
    const float* x         = (const float*)d_in[0];
    const int*   ei        = (const int*)  d_in[1];
    const float* ea        = (const float*)d_in[2];
    const float* lin0_w    = (const float*)d_in[3];
    const float* lin0_b    = (const float*)d_in[4];
    const float* nn1_w     = (const float*)d_in[5];
    const float* nn1_b     = (const float*)d_in[6];
    const float* nn2_w     = (const float*)d_in[7];
    const float* nn2_b     = (const float*)d_in[8];
    const float* conv_root = (const float*)d_in[9];
    const float* conv_bias = (const float*)d_in[10];
    const float* w_ih      = (const float*)d_in[11];
    const float* w_hh      = (const float*)d_in[12];
    const float* b_ih      = (const float*)d_in[13];
    const float* b_hh      = (const float*)d_in[14];

    float* outp = nullptr;
    cudaGetSymbolAddress((void**)&outp, g_out);

    k_init<<<(N_NODES + 255) / 256, 256>>>();
    k_lin0<<<(N_NODES * DIM + 255) / 256, 256>>>(x, lin0_w, lin0_b);
    k_hepre<<<(N_EDGES * DIM + 255) / 256, 256>>>(ea, ei, nn1_w, nn1_b);
    k_scan<<<2, 1024>>>();
    k_scatter<<<(N_EDGES + 255) / 256, 256>>>(ei);

    for (int r = 0; r < 6; ++r) {
        k_msg<<<N_NODES / 16, 256>>>(nn2_w, nn2_b);
        k_upd<<<N_NODES / 16, 256>>>(conv_root, conv_bias, w_ih, w_hh, b_ih, b_hh,
                                     r == 5 ? (float*)d_out : outp);
    }
}

// round 3
// speedup vs baseline: 2.3628x; 1.2426x over previous
#include <cuda_runtime.h>
#include <math.h>
#include <stdint.h>

#define N_NODES 12800
#define N_EDGES 204800
#define DIM 16

// ---------------- scratch (static device memory, no allocs) ----------------
__device__ float g_out[N_NODES * DIM];
__device__ float g_he[N_EDGES * DIM];      // edge hidden, edge order
__device__ float g_hs[N_EDGES * DIM];      // edge hidden, src-sorted order
__device__ int   g_qs[N_EDGES];            // src-sorted slot -> dst-sorted slot
__device__ float g_msg[N_EDGES * DIM];     // messages in dst-sorted order
__device__ int   g_src_cnt[N_NODES];       // zero at load; re-zeroed by k_scatter
__device__ int   g_dst_cnt[N_NODES];
__device__ int   g_src_off[N_NODES + 1];
__device__ int   g_dst_off[N_NODES + 1];
__device__ int   g_src_cur[N_NODES];
__device__ int   g_dst_cur[N_NODES];
__device__ float g_invdeg[N_NODES];

// ---------------- setup ----------------
// Fused: edge hidden + degree histograms (blocks 0..12799) and lin0 (blocks 12800..13599)
__global__ void k_prep(const float* __restrict__ x, const int* __restrict__ ei,
                       const float* __restrict__ ea,
                       const float* __restrict__ l0w, const float* __restrict__ l0b,
                       const float* __restrict__ n1w, const float* __restrict__ n1b) {
    int gb = blockIdx.x;
    if (gb < (N_EDGES * DIM) / 256) {
        int i = gb * 256 + threadIdx.x;            // [0, N_EDGES*16)
        int e = i >> 4, j = i & 15;
        float acc = n1b[j];
#pragma unroll
        for (int c = 0; c < 4; ++c) acc += ea[e * 4 + c] * n1w[j * 4 + c];
        g_he[i] = fmaxf(acc, 0.0f);
        if (j == 0) {
            atomicAdd(&g_src_cnt[ei[e]], 1);
            atomicAdd(&g_dst_cnt[ei[N_EDGES + e]], 1);
        }
    } else {
        int i = (gb - (N_EDGES * DIM) / 256) * 256 + threadIdx.x;  // [0, N_NODES*16)
        int n = i >> 4, k = i & 15;
        float acc = l0b[k];
#pragma unroll
        for (int c = 0; c < 3; ++c) acc += x[n * 3 + c] * l0w[k * 3 + c];
        g_out[i] = fmaxf(acc, 0.0f);
    }
}

// Shuffle-based exclusive scan; block 0 = src, block 1 = dst (+invdeg). 2 barriers.
__global__ void k_scan() {
    const int PER = 13;                            // 1024*13 >= 12800
    int which = blockIdx.x;
    int* cnt = which ? g_dst_cnt : g_src_cnt;
    int* off = which ? g_dst_off : g_src_off;
    int* cur = which ? g_dst_cur : g_src_cur;
    int tid = threadIdx.x, lane = tid & 31, wid = tid >> 5;
    int base = tid * PER;
    int c[PER];
    int local = 0;
#pragma unroll
    for (int i = 0; i < PER; ++i) {
        int idx = base + i;
        c[i] = (idx < N_NODES) ? cnt[idx] : 0;
        local += c[i];
    }
    int incl = local;
#pragma unroll
    for (int s = 1; s < 32; s <<= 1) {
        int v = __shfl_up_sync(0xffffffffu, incl, s);
        if (lane >= s) incl += v;
    }
    __shared__ int wsum[32];
    if (lane == 31) wsum[wid] = incl;
    __syncthreads();
    if (wid == 0) {
        int v = wsum[lane];
        int iv = v;
#pragma unroll
        for (int s = 1; s < 32; s <<= 1) {
            int t = __shfl_up_sync(0xffffffffu, iv, s);
            if (lane >= s) iv += t;
        }
        wsum[lane] = iv - v;                       // exclusive warp base
    }
    __syncthreads();
    int run = wsum[wid] + (incl - local);          // thread's exclusive prefix
#pragma unroll
    for (int i = 0; i < PER; ++i) {
        int idx = base + i;
        if (idx < N_NODES) {
            off[idx] = run;
            cur[idx] = run;
            if (which) g_invdeg[idx] = 1.0f / fmaxf((float)c[i], 1.0f);
            run += c[i];
        }
    }
    if (tid == 1023) off[N_NODES] = run;           // == N_EDGES
}

// Place each edge: gather h_e into src-sorted order, record its dst slot.
// Also re-zeroes the count arrays for the next kernel_launch call.
__global__ void k_scatter(const int* __restrict__ ei) {
    int e = blockIdx.x * blockDim.x + threadIdx.x;
    if (e >= N_EDGES) return;
    int s = ei[e], d = ei[N_EDGES + e];
    int p = atomicAdd(&g_src_cur[s], 1);
    int q = atomicAdd(&g_dst_cur[d], 1);
    g_qs[p] = q;
    const float4* hsrc = (const float4*)&g_he[e * DIM];
    float4* hdst = (float4*)&g_hs[p * DIM];
    hdst[0] = hsrc[0]; hdst[1] = hsrc[1]; hdst[2] = hsrc[2]; hdst[3] = hsrc[3];
    if (e < N_NODES) { g_src_cnt[e] = 0; g_dst_cnt[e] = 0; }
}

// ---------------- per-round kernels ----------------
// k_msg: 128 threads = 32 nodes x 4 lanes. Each lane owns k = l*4..l*4+3,
// holds P[kk][j] as 32 packed f32x2 regs, streams its node's src-sorted edges.
__global__ void __launch_bounds__(128) k_msg(const float* __restrict__ w2,
                                             const float* __restrict__ b2) {
    __shared__ unsigned long long s_w2p[16 * 8 * 16];  // [d][jj][k], j-pairs packed, 16KB
    __shared__ float s_b2[256];                        // [d][k]
    __shared__ float s_out[32][17];
    int tid = threadIdx.x;
    for (int i = tid; i < 4096; i += 128) {
        int d = i >> 8, k = (i >> 4) & 15, j = i & 15;
        ((float*)&s_w2p[(d * 8 + (j >> 1)) * 16 + k])[j & 1] = w2[i];
    }
    for (int i = tid; i < 256; i += 128) s_b2[i] = b2[i];
    int nb = blockIdx.x * 32;
    for (int i = tid; i < 32 * DIM; i += 128) s_out[i >> 4][i & 15] = g_out[nb * DIM + i];
    __syncthreads();

    int l = tid & 3;                                   // k-quad index
    int g = tid >> 2;                                  // node within block
    int n = nb + g;

    unsigned long long p2[32];                         // [kk][jj]
    float xb[4];
#pragma unroll
    for (int i = 0; i < 32; ++i) p2[i] = 0ull;
#pragma unroll
    for (int kk = 0; kk < 4; ++kk) xb[kk] = 0.0f;
#pragma unroll
    for (int d = 0; d < 16; ++d) {
        float od = s_out[g][d];
        unsigned long long od2;
        asm("mov.b64 %0,{%1,%1};" : "=l"(od2) : "f"(od));
#pragma unroll
        for (int kk = 0; kk < 4; ++kk) {
            int k = l * 4 + kk;
            xb[kk] += od * s_b2[d * 16 + k];
#pragma unroll
            for (int jj = 0; jj < 8; ++jj) {
                unsigned long long w = s_w2p[(d * 8 + jj) * 16 + k];
                asm("fma.rn.f32x2 %0,%1,%2,%0;" : "+l"(p2[kk * 8 + jj]) : "l"(od2), "l"(w));
            }
        }
    }

    int beg = g_src_off[n], end = g_src_off[n + 1];
    const ulonglong2* hsp = (const ulonglong2*)g_hs;
    for (int i = beg; i < end; ++i) {
        int q = __ldg(&g_qs[i]);
        ulonglong2 A = hsp[i * 4 + 0], B = hsp[i * 4 + 1];
        ulonglong2 C = hsp[i * 4 + 2], D = hsp[i * 4 + 3];
        float4 m4;
        float* mm = (float*)&m4;
#pragma unroll
        for (int kk = 0; kk < 4; ++kk) {
            unsigned long long acc;
            asm("mul.rn.f32x2 %0,%1,%2;" : "=l"(acc) : "l"(A.x), "l"(p2[kk * 8 + 0]));
            asm("fma.rn.f32x2 %0,%1,%2,%0;" : "+l"(acc) : "l"(A.y), "l"(p2[kk * 8 + 1]));
            asm("fma.rn.f32x2 %0,%1,%2,%0;" : "+l"(acc) : "l"(B.x), "l"(p2[kk * 8 + 2]));
            asm("fma.rn.f32x2 %0,%1,%2,%0;" : "+l"(acc) : "l"(B.y), "l"(p2[kk * 8 + 3]));
            asm("fma.rn.f32x2 %0,%1,%2,%0;" : "+l"(acc) : "l"(C.x), "l"(p2[kk * 8 + 4]));
            asm("fma.rn.f32x2 %0,%1,%2,%0;" : "+l"(acc) : "l"(C.y), "l"(p2[kk * 8 + 5]));
            asm("fma.rn.f32x2 %0,%1,%2,%0;" : "+l"(acc) : "l"(D.x), "l"(p2[kk * 8 + 6]));
            asm("fma.rn.f32x2 %0,%1,%2,%0;" : "+l"(acc) : "l"(D.y), "l"(p2[kk * 8 + 7]));
            float lo, hi;
            asm("mov.b64 {%0,%1},%2;" : "=f"(lo), "=f"(hi) : "l"(acc));
            mm[kk] = lo + hi + xb[kk];
        }
        ((float4*)g_msg)[q * 4 + l] = m4;              // 64B per edge, coalesced in group
    }
}

// k_upd: contiguous message mean + root matmul + ReLU + GRU. 16 nodes x 16 k.
__global__ void k_upd(const float* __restrict__ cr, const float* __restrict__ cb,
                      const float* __restrict__ wih, const float* __restrict__ whh,
                      const float* __restrict__ bih, const float* __restrict__ bhh,
                      float* __restrict__ outw) {
    __shared__ float s_cr[DIM * DIM];
    __shared__ float s_wih[DIM * 3 * DIM];   // transposed [d][r]
    __shared__ float s_whh[DIM * 3 * DIM];
    __shared__ float s_out[16][DIM];
    __shared__ float s_m[16][DIM];
    int tid = threadIdx.x;
    for (int i = tid; i < DIM * DIM; i += 256) s_cr[i] = cr[i];
    for (int i = tid; i < 3 * DIM * DIM; i += 256) {
        int r = i >> 4, d = i & 15;
        s_wih[d * 48 + r] = wih[i];
        s_whh[d * 48 + r] = whh[i];
    }
    int ln = tid >> 4, k = tid & 15;
    int n = blockIdx.x * 16 + ln;
    float hprev = g_out[n * DIM + k];
    s_out[ln][k] = hprev;
    __syncthreads();

    int beg = g_dst_off[n], end = g_dst_off[n + 1];
    float acc = 0.0f;
    for (int q = beg; q < end; ++q) acc += g_msg[q * DIM + k];
    acc = acc * g_invdeg[n] + cb[k];
#pragma unroll
    for (int d = 0; d < DIM; ++d) acc += s_out[ln][d] * s_cr[d * DIM + k];
    float m = fmaxf(acc, 0.0f);
    s_m[ln][k] = m;
    __syncthreads();

    float gr = bih[k], gz = bih[k + 16], gn = bih[k + 32];
    float hr = bhh[k], hz = bhh[k + 16], hn = bhh[k + 32];
#pragma unroll
    for (int d = 0; d < DIM; ++d) {
        float md = s_m[ln][d], hd = s_out[ln][d];
        gr += md * s_wih[d * 48 + k];
        gz += md * s_wih[d * 48 + k + 16];
        gn += md * s_wih[d * 48 + k + 32];
        hr += hd * s_whh[d * 48 + k];
        hz += hd * s_whh[d * 48 + k + 16];
        hn += hd * s_whh[d * 48 + k + 32];
    }
    float r = 1.0f / (1.0f + expf(-(gr + hr)));
    float z = 1.0f / (1.0f + expf(-(gz + hz)));
    float nh = tanhf(gn + r * hn);
    outw[n * DIM + k] = (1.0f - z) * nh + z * hprev;
}

// ---------------- host launcher ----------------
extern "C" void kernel_launch(void* const* d_in, const int* in_sizes, int n_in,
                              void* d_out, int out_size) {
    const float* x         = (const float*)d_in[0];
    const int*   ei        = (const int*)  d_in[1];
    const float* ea        = (const float*)d_in[2];
    const float* lin0_w    = (const float*)d_in[3];
    const float* lin0_b    = (const float*)d_in[4];
    const float* nn1_w     = (const float*)d_in[5];
    const float* nn1_b     = (const float*)d_in[6];
    const float* nn2_w     = (const float*)d_in[7];
    const float* nn2_b     = (const float*)d_in[8];
    const float* conv_root = (const float*)d_in[9];
    const float* conv_bias = (const float*)d_in[10];
    const float* w_ih      = (const float*)d_in[11];
    const float* w_hh      = (const float*)d_in[12];
    const float* b_ih      = (const float*)d_in[13];
    const float* b_hh      = (const float*)d_in[14];

    float* outp = nullptr;
    cudaGetSymbolAddress((void**)&outp, g_out);

    k_prep<<<(N_EDGES * DIM) / 256 + (N_NODES * DIM) / 256, 256>>>(
        x, ei, ea, lin0_w, lin0_b, nn1_w, nn1_b);
    k_scan<<<2, 1024>>>();
    k_scatter<<<(N_EDGES + 255) / 256, 256>>>(ei);

    for (int r = 0; r < 6; ++r) {
        k_msg<<<N_NODES / 32, 128>>>(nn2_w, nn2_b);
        k_upd<<<N_NODES / 16, 256>>>(conv_root, conv_bias, w_ih, w_hh, b_ih, b_hh,
                                     r == 5 ? (float*)d_out : outp);
    }
}